// round 1
// baseline (speedup 1.0000x reference)
#include <cuda_runtime.h>
#include <cstdint>

// NGP hash-grid interpolation encoding.
// B=262144 points (x in [0,1)^3), L=16 levels, T=19 (2^19-entry tables), F=2.
// out[b, l*2 + f] = sum_{v=0..7} w_v * tables[l, hash(corner_v) & MASK, f]

constexpr int   LVL   = 16;
constexpr int   BLK   = 256;
constexpr uint32_t MASK19 = (1u << 19) - 1u;
constexpr uint32_t P1 = 2654435761u;
constexpr uint32_t P2 = 805459861u;

// RES[l] = floor(16 * (2^(1/3))^l), computed in float64 to match numpy reference.
__constant__ float RES_C[LVL] = {
    16.f, 20.f, 25.f, 32.f, 40.f, 50.f, 64.f, 80.f,
    101.f, 128.f, 161.f, 203.f, 256.f, 322.f, 406.f, 512.f
};

__global__ __launch_bounds__(BLK)
void ngp_enc_kernel(const float* __restrict__ x,
                    const float* __restrict__ tables,
                    float* __restrict__ out,
                    int B)
{
    int b = blockIdx.x * BLK + threadIdx.x;
    if (b >= B) return;

    const float x0 = x[3 * b + 0];
    const float x1 = x[3 * b + 1];
    const float x2 = x[3 * b + 2];

    float acc[2 * LVL];

    #pragma unroll
    for (int l = 0; l < LVL; ++l) {
        const float r = RES_C[l];
        const float s0 = x0 * r;
        const float s1 = x1 * r;
        const float s2 = x2 * r;
        const float f0 = floorf(s0);
        const float f1 = floorf(s1);
        const float f2 = floorf(s2);
        const float fr0 = s0 - f0;
        const float fr1 = s1 - f1;
        const float fr2 = s2 - f2;

        const uint32_t g0 = (uint32_t)f0;
        const uint32_t g1 = (uint32_t)f1;
        const uint32_t g2 = (uint32_t)f2;

        // Per-dim hash contributions for border bit 0 / 1.
        const uint32_t h0a = g0;                 // * PRIMES[0] == 1
        const uint32_t h0b = g0 + 1u;
        const uint32_t h1a = g1 * P1;
        const uint32_t h1b = h1a + P1;
        const uint32_t h2a = g2 * P2;
        const uint32_t h2b = h2a + P2;

        const float2* __restrict__ tbl =
            reinterpret_cast<const float2*>(tables) + ((size_t)l << 19);

        // Compute all 8 indices first, then issue all 8 loads (MLP=8).
        uint32_t idx[8];
        #pragma unroll
        for (int v = 0; v < 8; ++v) {
            uint32_t h = ((v & 1) ? h0b : h0a)
                       ^ ((v & 2) ? h1b : h1a)
                       ^ ((v & 4) ? h2b : h2a);
            idx[v] = h & MASK19;
        }

        float2 t[8];
        #pragma unroll
        for (int v = 0; v < 8; ++v) {
            t[v] = __ldg(&tbl[idx[v]]);
        }

        const float w0a = 1.0f - fr0, w0b = fr0;
        const float w1a = 1.0f - fr1, w1b = fr1;
        const float w2a = 1.0f - fr2, w2b = fr2;

        float a0 = 0.0f, a1 = 0.0f;
        #pragma unroll
        for (int v = 0; v < 8; ++v) {
            float w = (((v & 1) ? w0b : w0a) * ((v & 2) ? w1b : w1a))
                    * ((v & 4) ? w2b : w2a);
            a0 = fmaf(w, t[v].x, a0);
            a1 = fmaf(w, t[v].y, a1);
        }
        acc[2 * l + 0] = a0;
        acc[2 * l + 1] = a1;
    }

    // 32 contiguous floats per point -> 8 x STG.128 (full-sector stores).
    float4* o = reinterpret_cast<float4*>(out + (size_t)b * (2 * LVL));
    #pragma unroll
    for (int i = 0; i < 2 * LVL / 4; ++i) {
        o[i] = make_float4(acc[4 * i + 0], acc[4 * i + 1],
                           acc[4 * i + 2], acc[4 * i + 3]);
    }
}

extern "C" void kernel_launch(void* const* d_in, const int* in_sizes, int n_in,
                              void* d_out, int out_size)
{
    const float* x      = (const float*)d_in[0];
    const float* tables = (const float*)d_in[1];
    float* out          = (float*)d_out;

    const int B = in_sizes[0] / 3;
    const int grid = (B + BLK - 1) / BLK;
    ngp_enc_kernel<<<grid, BLK>>>(x, tables, out, B);
}